// round 3
// baseline (speedup 1.0000x reference)
#include <cuda_runtime.h>
#include <cstdint>

// ============================================================================
// InteractAttention on sm_103 (no 'a' features available from this toolchain):
//   6 GEMMs via mma.sync.m16n8k8.tf32 (fp32 accum) -> scratch -> fused epilogue
//   g=0: xc@LW1  g=1: xc@AW12  g=2: xc@AW2  g=3: xp@LW2  g=4: xp@AW1  g=5: xp@AW23
// ============================================================================

#define B_ROWS   32768
#define H_DIM    256
#define MT       128                  // CTA M tile
#define NT       256                  // CTA N tile (= full H)
#define KCH      32                   // K chunk
#define STAGES   3
#define NTHREADS 512
#define N_ROW_TILES (B_ROWS / MT)     // 256
#define SCRATCH_PER 8388608ull        // B_ROWS * H_DIM

__device__ float g_scratch[6ull * SCRATCH_PER];

// smem strides (floats) chosen for conflict-free fragment reads
#define A_STRIDE 36                   // 128 rows x 36
#define B_STRIDE 264                  // 32 rows x 264
#define A_BYTES  (MT * A_STRIDE * 4)          // 18432
#define B_BYTES  (KCH * B_STRIDE * 4)         // 33792
#define STAGE_BYTES (A_BYTES + B_BYTES)       // 52224
#define SMEM_BYTES  (STAGES * STAGE_BYTES)    // 156672

__device__ __forceinline__ uint32_t smem_u32(const void* p) {
    uint32_t a;
    asm("{ .reg .u64 t; cvta.to.shared.u64 t, %1; cvt.u32.u64 %0, t; }"
        : "=r"(a) : "l"(p));
    return a;
}
__device__ __forceinline__ void cp16(uint32_t dst, const void* src) {
    asm volatile("cp.async.cg.shared.global [%0], [%1], 16;" :: "r"(dst), "l"(src));
}
__device__ __forceinline__ uint32_t f2tf32(float v) {
    uint32_t r;
    asm("cvt.rna.tf32.f32 %0, %1;" : "=r"(r) : "f"(v));
    return r;
}
__device__ __forceinline__ void mma_tf32(float* c, const uint32_t* a, const uint32_t* b) {
    asm volatile(
        "mma.sync.aligned.m16n8k8.row.col.f32.tf32.tf32.f32 "
        "{%0,%1,%2,%3}, {%4,%5,%6,%7}, {%8,%9}, {%0,%1,%2,%3};"
        : "+f"(c[0]), "+f"(c[1]), "+f"(c[2]), "+f"(c[3])
        : "r"(a[0]), "r"(a[1]), "r"(a[2]), "r"(a[3]), "r"(b[0]), "r"(b[1]));
}

__global__ void __launch_bounds__(NTHREADS, 1)
gemm_tf32_kernel(const float* __restrict__ xc, const float* __restrict__ xp,
                 const float* __restrict__ w0, const float* __restrict__ w1,
                 const float* __restrict__ w2, const float* __restrict__ w3,
                 const float* __restrict__ w4, const float* __restrict__ w5) {
    extern __shared__ float smem[];
    const int tid = threadIdx.x;
    const int wid = tid >> 5;
    const int lid = tid & 31;
    const int g8  = lid >> 2;          // 0..7
    const int tg  = lid & 3;           // 0..3
    const int wm  = wid & 3;           // warp M index (0..3) -> rows wm*32..+31
    const int wn  = wid >> 2;          // warp N index (0..3) -> cols wn*64..+63

    const int bid  = blockIdx.x;
    const int g    = bid % 6;
    const int tile = bid / 6;

    const float* X; const float* W; int K;
    if      (g == 0) { X = xc; W = w0; K = 768;  }
    else if (g == 1) { X = xc; W = w1; K = 768;  }
    else if (g == 2) { X = xc; W = w2; K = 768;  }
    else if (g == 3) { X = xp; W = w3; K = 2048; }
    else if (g == 4) { X = xp; W = w4; K = 2048; }
    else             { X = xp; W = w5; K = 2048; }

    const float* Xb = X + (size_t)tile * MT * K;
    float* Y = g_scratch + (size_t)g * SCRATCH_PER + (size_t)tile * (MT * H_DIM);

    const uint32_t sb = smem_u32(smem);
    const int NK = K >> 5;

    float c[2][8][4];
    #pragma unroll
    for (int mt = 0; mt < 2; mt++)
        #pragma unroll
        for (int nt = 0; nt < 8; nt++)
            #pragma unroll
            for (int r = 0; r < 4; r++) c[mt][nt][r] = 0.0f;

    // ---- stage loader: A 1024 cp16 + B 2048 cp16 over 512 threads ----
    auto load_stage = [&](int chunk) {
        const int st = chunk % STAGES;
        const uint32_t stA = sb + st * STAGE_BYTES;
        const uint32_t stB = stA + A_BYTES;
        const int kc = chunk * KCH;
        // A: 128 rows x 8 vec16
        #pragma unroll
        for (int i = 0; i < 2; i++) {
            const int f   = tid + i * NTHREADS;       // [0,1024)
            const int row = f >> 3;
            const int v   = f & 7;
            cp16(stA + row * (A_STRIDE * 4) + v * 16,
                 Xb + (size_t)row * K + kc + v * 4);
        }
        // B: 32 rows x 64 vec16
        #pragma unroll
        for (int i = 0; i < 4; i++) {
            const int f = tid + i * NTHREADS;         // [0,2048)
            const int k = f >> 6;
            const int v = f & 63;
            cp16(stB + k * (B_STRIDE * 4) + v * 16,
                 W + (size_t)(kc + k) * H_DIM + v * 4);
        }
    };

    // prologue
    #pragma unroll
    for (int s = 0; s < STAGES - 1; s++) {
        load_stage(s);
        asm volatile("cp.async.commit_group;" ::: "memory");
    }

    for (int i = 0; i < NK; i++) {
        if (i + STAGES - 1 < NK) load_stage(i + STAGES - 1);
        asm volatile("cp.async.commit_group;" ::: "memory");
        asm volatile("cp.async.wait_group %0;" :: "n"(STAGES - 1) : "memory");
        __syncthreads();

        const int st = i % STAGES;
        const float* As = smem + st * (STAGE_BYTES / 4);
        const float* Bs = As + (A_BYTES / 4);

        #pragma unroll
        for (int k8 = 0; k8 < 4; k8++) {
            const int k0 = k8 * 8;
            uint32_t a[2][4];
            #pragma unroll
            for (int mt = 0; mt < 2; mt++) {
                const int r0 = wm * 32 + mt * 16 + g8;
                a[mt][0] = f2tf32(As[r0 * A_STRIDE + k0 + tg]);
                a[mt][1] = f2tf32(As[(r0 + 8) * A_STRIDE + k0 + tg]);
                a[mt][2] = f2tf32(As[r0 * A_STRIDE + k0 + tg + 4]);
                a[mt][3] = f2tf32(As[(r0 + 8) * A_STRIDE + k0 + tg + 4]);
            }
            uint32_t b[8][2];
            #pragma unroll
            for (int nt = 0; nt < 8; nt++) {
                const int n = wn * 64 + nt * 8 + g8;
                b[nt][0] = f2tf32(Bs[(k0 + tg) * B_STRIDE + n]);
                b[nt][1] = f2tf32(Bs[(k0 + tg + 4) * B_STRIDE + n]);
            }
            #pragma unroll
            for (int mt = 0; mt < 2; mt++)
                #pragma unroll
                for (int nt = 0; nt < 8; nt++)
                    mma_tf32(c[mt][nt], a[mt], b[nt]);
        }
        __syncthreads();
    }

    // ---- writeback: float2 per fragment half ----
    #pragma unroll
    for (int mt = 0; mt < 2; mt++) {
        const int r0 = wm * 32 + mt * 16 + g8;
        #pragma unroll
        for (int nt = 0; nt < 8; nt++) {
            const int col = wn * 64 + nt * 8 + tg * 2;
            *(float2*)(Y + (size_t)r0 * H_DIM + col) =
                make_float2(c[mt][nt][0], c[mt][nt][1]);
            *(float2*)(Y + (size_t)(r0 + 8) * H_DIM + col) =
                make_float2(c[mt][nt][2], c[mt][nt][3]);
        }
    }
}

// ---------------- epilogue: one warp per row ----------------
__device__ __forceinline__ float wsum(float v) {
    #pragma unroll
    for (int o = 16; o; o >>= 1) v += __shfl_xor_sync(0xFFFFFFFFu, v, o);
    return v;
}
__device__ __forceinline__ void load8(float* a, const float* base, int lane) {
    const float4* p = (const float4*)base;
    float4 x = p[lane], y = p[lane + 32];
    a[0]=x.x; a[1]=x.y; a[2]=x.z; a[3]=x.w;
    a[4]=y.x; a[5]=y.y; a[6]=y.z; a[7]=y.w;
}
__device__ __forceinline__ void store8(float* base, const float* a, int lane) {
    float4* p = (float4*)base;
    p[lane]      = make_float4(a[0], a[1], a[2], a[3]);
    p[lane + 32] = make_float4(a[4], a[5], a[6], a[7]);
}
__device__ __forceinline__ float sigm(float x) { return 1.0f / (1.0f + expf(-x)); }

__global__ void __launch_bounds__(256)
epilogue_kernel(const float* __restrict__ lb1, const float* __restrict__ lb2,
                float* __restrict__ out) {
    const int lane = threadIdx.x & 31;
    const int row  = blockIdx.x * 8 + (threadIdx.x >> 5);
    const size_t off = (size_t)row * H_DIM;

    const float* S0 = g_scratch + 0 * SCRATCH_PER + off;  // xc@LW1
    const float* S1 = g_scratch + 1 * SCRATCH_PER + off;  // xc@AW12
    const float* S2 = g_scratch + 2 * SCRATCH_PER + off;  // xc@AW2
    const float* S3 = g_scratch + 3 * SCRATCH_PER + off;  // xp@LW2
    const float* S4 = g_scratch + 4 * SCRATCH_PER + off;  // xp@AW1
    const float* S5 = g_scratch + 5 * SCRATCH_PER + off;  // xp@AW23

    float cb[8], a12[8], a2[8], pb[8], a1[8], a23[8], b1[8], b2[8];
    load8(cb, S0, lane);  load8(a12, S1, lane); load8(a2, S2, lane);
    load8(pb, S3, lane);  load8(a1, S4, lane);  load8(a23, S5, lane);
    load8(b1, lb1, lane); load8(b2, lb2, lane);

    float s_cw = 0.f, s_pw1 = 0.f, s_num = 0.f, s_cc = 0.f, s_pp = 0.f;
    float pwv[8], cw1[8];
    #pragma unroll
    for (int j = 0; j < 8; j++) {
        cb[j] += b1[j];
        pb[j] += b2[j];
        pwv[j] = pb[j] * sigm(a1[j]);              // p_w
        cw1[j] = cb[j] * sigm(a2[j]);              // c_w1
        s_cw  += cb[j] * sigm(a12[j]);             // sum c_w
        s_pw1 += pb[j] * sigm(a23[j]);             // sum p_w1
        s_num += cb[j] * pb[j];
        s_cc  += cb[j] * cb[j];
        s_pp  += pb[j] * pb[j];
    }
    s_cw  = wsum(s_cw)  * (1.0f / 256.0f);
    s_pw1 = wsum(s_pw1) * (1.0f / 256.0f);
    s_num = wsum(s_num);
    s_cc  = wsum(s_cc);
    s_pp  = wsum(s_pp);
    const float sim = s_num / (sqrtf(s_cc) * sqrtf(s_pp));

    float co[8], po[8];
    #pragma unroll
    for (int j = 0; j < 8; j++) {
        co[j] = sigm(cb[j]) * tanhf(pwv[j] * s_cw);
        po[j] = sigm(pb[j]) * tanhf(cw1[j] * s_pw1) * sim;
    }
    store8(out + off, co, lane);
    store8(out + (size_t)B_ROWS * H_DIM + off, po, lane);
}

// ---------------- launch ----------------
extern "C" void kernel_launch(void* const* d_in, const int* in_sizes, int n_in,
                              void* d_out, int out_size) {
    const float* xc  = (const float*)d_in[0];
    const float* xp  = (const float*)d_in[1];
    const float* LW1 = (const float*)d_in[2];
    const float* LB1 = (const float*)d_in[3];
    const float* LW2 = (const float*)d_in[4];
    const float* LB2 = (const float*)d_in[5];
    const float* AW1 = (const float*)d_in[6];
    const float* AW12= (const float*)d_in[7];
    const float* AW2 = (const float*)d_in[8];
    const float* AW23= (const float*)d_in[9];
    float* out = (float*)d_out;

    cudaFuncSetAttribute(gemm_tf32_kernel,
                         cudaFuncAttributeMaxDynamicSharedMemorySize, SMEM_BYTES);

    gemm_tf32_kernel<<<N_ROW_TILES * 6, NTHREADS, SMEM_BYTES>>>(
        xc, xp, LW1, AW12, AW2, LW2, AW1, AW23);

    epilogue_kernel<<<B_ROWS / 8, 256>>>(LB1, LB2, out);
}

// round 4
// speedup vs baseline: 1.1007x; 1.1007x over previous
#include <cuda_runtime.h>
#include <cstdint>

// ============================================================================
// InteractAttention on sm_103 (base target; no tcgen05 available):
//   pre-round weights to tf32 -> 6 GEMMs via mma.sync.m16n8k8.tf32 -> scratch
//   -> fused row epilogue.
//   g=0: xc@LW1  g=1: xc@AW12  g=2: xc@AW2  g=3: xp@LW2  g=4: xp@AW1  g=5: xp@AW23
// ============================================================================

#define B_ROWS   32768
#define H_DIM    256
#define MT       128                  // CTA M tile
#define KCH      32                   // K chunk
#define STAGES   4
#define NTHREADS 512
#define N_ROW_TILES (B_ROWS / MT)     // 256
#define SCRATCH_PER 8388608ull        // B_ROWS * H_DIM

__device__ float g_scratch[6ull * SCRATCH_PER];
__device__ float g_wr[2162688];       // tf32-rounded weights, 6 matrices packed

// float offsets of each rounded weight matrix inside g_wr
#define WR0 0u          // LW1  768x256
#define WR1 196608u     // AW12 768x256
#define WR2 393216u     // AW2  768x256
#define WR3 589824u     // LW2  2048x256
#define WR4 1114112u    // AW1  2048x256
#define WR5 1638400u    // AW23 2048x256

// smem strides (floats) chosen for conflict-free fragment reads
#define A_STRIDE 36                   // bank = 4*g8 + tg : all 32 distinct
#define B_STRIDE 264                  // bank = 8*tg + g8 : all 32 distinct
#define A_BYTES  (MT * A_STRIDE * 4)          // 18432
#define B_BYTES  (KCH * B_STRIDE * 4)         // 33792
#define STAGE_BYTES (A_BYTES + B_BYTES)       // 52224
#define SMEM_BYTES  (STAGES * STAGE_BYTES)    // 208896

__device__ __forceinline__ uint32_t smem_u32(const void* p) {
    uint32_t a;
    asm("{ .reg .u64 t; cvta.to.shared.u64 t, %1; cvt.u32.u64 %0, t; }"
        : "=r"(a) : "l"(p));
    return a;
}
__device__ __forceinline__ void cp16(uint32_t dst, const void* src) {
    asm volatile("cp.async.cg.shared.global [%0], [%1], 16;" :: "r"(dst), "l"(src));
}
__device__ __forceinline__ uint32_t f2tf32(float v) {
    uint32_t r;
    asm("cvt.rna.tf32.f32 %0, %1;" : "=r"(r) : "f"(v));
    return r;
}
__device__ __forceinline__ void mma_tf32(float* c, const uint32_t* a, const uint32_t* b) {
    asm volatile(
        "mma.sync.aligned.m16n8k8.row.col.f32.tf32.tf32.f32 "
        "{%0,%1,%2,%3}, {%4,%5,%6,%7}, {%8,%9}, {%0,%1,%2,%3};"
        : "+f"(c[0]), "+f"(c[1]), "+f"(c[2]), "+f"(c[3])
        : "r"(a[0]), "r"(a[1]), "r"(a[2]), "r"(a[3]), "r"(b[0]), "r"(b[1]));
}

// ---------------- weight pre-rounding: 540672 float4 over 1056x512 ----------
__global__ void __launch_bounds__(512)
wround_kernel(const float* __restrict__ s0, const float* __restrict__ s1,
              const float* __restrict__ s2, const float* __restrict__ s3,
              const float* __restrict__ s4, const float* __restrict__ s5) {
    const unsigned f = blockIdx.x * 512u + threadIdx.x;   // float4 index
    const float* src; unsigned off;
    if      (f <  49152u) { src = s0; off = f; }
    else if (f <  98304u) { src = s1; off = f -  49152u; }
    else if (f < 147456u) { src = s2; off = f -  98304u; }
    else if (f < 278528u) { src = s3; off = f - 147456u; }
    else if (f < 409600u) { src = s4; off = f - 278528u; }
    else                  { src = s5; off = f - 409600u; }
    float4 v = ((const float4*)src)[off];
    uint4 r;
    r.x = f2tf32(v.x); r.y = f2tf32(v.y); r.z = f2tf32(v.z); r.w = f2tf32(v.w);
    ((uint4*)g_wr)[f] = r;
}

// ---------------- GEMM ----------------
__global__ void __launch_bounds__(NTHREADS, 1)
gemm_tf32_kernel(const float* __restrict__ xc, const float* __restrict__ xp) {
    extern __shared__ float smem[];
    const int tid = threadIdx.x;
    const int wid = tid >> 5;
    const int lid = tid & 31;
    const int g8  = lid >> 2;          // 0..7
    const int tg  = lid & 3;           // 0..3
    const int wm  = wid & 3;           // warp M index -> rows wm*32..+31
    const int wn  = wid >> 2;          // warp N index -> cols wn*64..+63

    // pic (K=2048) CTAs first; 3 same-tile CTAs adjacent for L2 A-sharing
    const int bid = blockIdx.x;
    int g, tile;
    if (bid < 3 * N_ROW_TILES) { tile = bid / 3; g = 3 + bid % 3; }
    else { const int b2 = bid - 3 * N_ROW_TILES; tile = b2 / 3; g = b2 % 3; }

    const float* X; const float* W; int K;
    if      (g == 0) { X = xc; W = g_wr + WR0; K = 768;  }
    else if (g == 1) { X = xc; W = g_wr + WR1; K = 768;  }
    else if (g == 2) { X = xc; W = g_wr + WR2; K = 768;  }
    else if (g == 3) { X = xp; W = g_wr + WR3; K = 2048; }
    else if (g == 4) { X = xp; W = g_wr + WR4; K = 2048; }
    else             { X = xp; W = g_wr + WR5; K = 2048; }

    const float* Xb = X + (size_t)tile * MT * K;
    float* Y = g_scratch + (size_t)g * SCRATCH_PER + (size_t)tile * (MT * H_DIM);

    const uint32_t sb = smem_u32(smem);
    const int NK = K >> 5;

    float c[2][8][4];
    #pragma unroll
    for (int mt = 0; mt < 2; mt++)
        #pragma unroll
        for (int nt = 0; nt < 8; nt++)
            #pragma unroll
            for (int r = 0; r < 4; r++) c[mt][nt][r] = 0.0f;

    // stage loader: A 1024 cp16 + B 2048 cp16 over 512 threads
    auto load_stage = [&](int chunk) {
        const int st = chunk % STAGES;
        const uint32_t stA = sb + st * STAGE_BYTES;
        const uint32_t stB = stA + A_BYTES;
        const int kc = chunk * KCH;
        #pragma unroll
        for (int i = 0; i < 2; i++) {                 // A: 128 rows x 8 vec16
            const int f   = tid + i * NTHREADS;
            const int row = f >> 3;
            const int v   = f & 7;
            cp16(stA + row * (A_STRIDE * 4) + v * 16,
                 Xb + (size_t)row * K + kc + v * 4);
        }
        #pragma unroll
        for (int i = 0; i < 4; i++) {                 // B: 32 rows x 64 vec16
            const int f = tid + i * NTHREADS;
            const int k = f >> 6;
            const int v = f & 63;
            cp16(stB + k * (B_STRIDE * 4) + v * 16,
                 W + (size_t)(kc + k) * H_DIM + v * 4);
        }
        asm volatile("cp.async.commit_group;" ::: "memory");
    };

    // prologue: chunks 0..STAGES-2
    #pragma unroll
    for (int s = 0; s < STAGES - 1; s++) load_stage(s);

    for (int i = 0; i < NK; i++) {
        asm volatile("cp.async.wait_group %0;" :: "n"(STAGES - 2) : "memory");
        __syncthreads();
        // issue next load AFTER the barrier: everyone is past compute(i-1),
        // whose buffer ((i-1)%STAGES == (i+STAGES-1)%STAGES) we now overwrite.
        if (i + STAGES - 1 < NK) load_stage(i + STAGES - 1);

        const int st = i % STAGES;
        const float* As = smem + st * (STAGE_BYTES / 4);
        const float* Bs = As + (A_BYTES / 4);

        #pragma unroll
        for (int k8 = 0; k8 < 4; k8++) {
            const int k0 = k8 * 8;
            uint32_t b[8][2];
            #pragma unroll
            for (int nt = 0; nt < 8; nt++) {          // B pre-rounded: no cvt
                const int n = wn * 64 + nt * 8 + g8;
                b[nt][0] = __float_as_uint(Bs[(k0 + tg) * B_STRIDE + n]);
                b[nt][1] = __float_as_uint(Bs[(k0 + tg + 4) * B_STRIDE + n]);
            }
            uint32_t a[2][4];
            #pragma unroll
            for (int mt = 0; mt < 2; mt++) {
                const int r0 = wm * 32 + mt * 16 + g8;
                a[mt][0] = f2tf32(As[r0 * A_STRIDE + k0 + tg]);
                a[mt][1] = f2tf32(As[(r0 + 8) * A_STRIDE + k0 + tg]);
                a[mt][2] = f2tf32(As[r0 * A_STRIDE + k0 + tg + 4]);
                a[mt][3] = f2tf32(As[(r0 + 8) * A_STRIDE + k0 + tg + 4]);
            }
            #pragma unroll
            for (int mt = 0; mt < 2; mt++)
                #pragma unroll
                for (int nt = 0; nt < 8; nt++)
                    mma_tf32(c[mt][nt], a[mt], b[nt]);
        }
    }

    // writeback
    #pragma unroll
    for (int mt = 0; mt < 2; mt++) {
        const int r0 = wm * 32 + mt * 16 + g8;
        #pragma unroll
        for (int nt = 0; nt < 8; nt++) {
            const int col = wn * 64 + nt * 8 + tg * 2;
            *(float2*)(Y + (size_t)r0 * H_DIM + col) =
                make_float2(c[mt][nt][0], c[mt][nt][1]);
            *(float2*)(Y + (size_t)(r0 + 8) * H_DIM + col) =
                make_float2(c[mt][nt][2], c[mt][nt][3]);
        }
    }
}

// ---------------- epilogue: one warp per row ----------------
__device__ __forceinline__ float wsum(float v) {
    #pragma unroll
    for (int o = 16; o; o >>= 1) v += __shfl_xor_sync(0xFFFFFFFFu, v, o);
    return v;
}
__device__ __forceinline__ void load8(float* a, const float* base, int lane) {
    const float4* p = (const float4*)base;
    float4 x = p[lane], y = p[lane + 32];
    a[0]=x.x; a[1]=x.y; a[2]=x.z; a[3]=x.w;
    a[4]=y.x; a[5]=y.y; a[6]=y.z; a[7]=y.w;
}
__device__ __forceinline__ void store8(float* base, const float* a, int lane) {
    float4* p = (float4*)base;
    p[lane]      = make_float4(a[0], a[1], a[2], a[3]);
    p[lane + 32] = make_float4(a[4], a[5], a[6], a[7]);
}
__device__ __forceinline__ float sigm(float x) {
    return 1.0f / (1.0f + __expf(-x));
}
__device__ __forceinline__ float tanh_fast(float x) {
    return 1.0f - 2.0f / (1.0f + __expf(2.0f * x));
}

__global__ void __launch_bounds__(256)
epilogue_kernel(const float* __restrict__ lb1, const float* __restrict__ lb2,
                float* __restrict__ out) {
    const int lane = threadIdx.x & 31;
    const int row  = blockIdx.x * 8 + (threadIdx.x >> 5);
    const size_t off = (size_t)row * H_DIM;

    const float* S0 = g_scratch + 0 * SCRATCH_PER + off;  // xc@LW1
    const float* S1 = g_scratch + 1 * SCRATCH_PER + off;  // xc@AW12
    const float* S2 = g_scratch + 2 * SCRATCH_PER + off;  // xc@AW2
    const float* S3 = g_scratch + 3 * SCRATCH_PER + off;  // xp@LW2
    const float* S4 = g_scratch + 4 * SCRATCH_PER + off;  // xp@AW1
    const float* S5 = g_scratch + 5 * SCRATCH_PER + off;  // xp@AW23

    float cb[8], a12[8], a2[8], pb[8], a1[8], a23[8], b1[8], b2[8];
    load8(cb, S0, lane);  load8(a12, S1, lane); load8(a2, S2, lane);
    load8(pb, S3, lane);  load8(a1, S4, lane);  load8(a23, S5, lane);
    load8(b1, lb1, lane); load8(b2, lb2, lane);

    float s_cw = 0.f, s_pw1 = 0.f, s_num = 0.f, s_cc = 0.f, s_pp = 0.f;
    float pwv[8], cw1[8];
    #pragma unroll
    for (int j = 0; j < 8; j++) {
        cb[j] += b1[j];
        pb[j] += b2[j];
        pwv[j] = pb[j] * sigm(a1[j]);              // p_w
        cw1[j] = cb[j] * sigm(a2[j]);              // c_w1
        s_cw  += cb[j] * sigm(a12[j]);             // sum c_w
        s_pw1 += pb[j] * sigm(a23[j]);             // sum p_w1
        s_num += cb[j] * pb[j];
        s_cc  += cb[j] * cb[j];
        s_pp  += pb[j] * pb[j];
    }
    s_cw  = wsum(s_cw)  * (1.0f / 256.0f);
    s_pw1 = wsum(s_pw1) * (1.0f / 256.0f);
    s_num = wsum(s_num);
    s_cc  = wsum(s_cc);
    s_pp  = wsum(s_pp);
    const float sim = s_num / (sqrtf(s_cc) * sqrtf(s_pp));

    float co[8], po[8];
    #pragma unroll
    for (int j = 0; j < 8; j++) {
        co[j] = sigm(cb[j]) * tanh_fast(pwv[j] * s_cw);
        po[j] = sigm(pb[j]) * tanh_fast(cw1[j] * s_pw1) * sim;
    }
    store8(out + off, co, lane);
    store8(out + (size_t)B_ROWS * H_DIM + off, po, lane);
}

// ---------------- launch ----------------
extern "C" void kernel_launch(void* const* d_in, const int* in_sizes, int n_in,
                              void* d_out, int out_size) {
    const float* xc  = (const float*)d_in[0];
    const float* xp  = (const float*)d_in[1];
    const float* LW1 = (const float*)d_in[2];
    const float* LB1 = (const float*)d_in[3];
    const float* LW2 = (const float*)d_in[4];
    const float* LB2 = (const float*)d_in[5];
    const float* AW1 = (const float*)d_in[6];
    const float* AW12= (const float*)d_in[7];
    const float* AW2 = (const float*)d_in[8];
    const float* AW23= (const float*)d_in[9];
    float* out = (float*)d_out;

    wround_kernel<<<1056, 512>>>(LW1, AW12, AW2, LW2, AW1, AW23);

    cudaFuncSetAttribute(gemm_tf32_kernel,
                         cudaFuncAttributeMaxDynamicSharedMemorySize, SMEM_BYTES);
    gemm_tf32_kernel<<<N_ROW_TILES * 6, NTHREADS, SMEM_BYTES>>>(xc, xp);

    epilogue_kernel<<<B_ROWS / 8, 256>>>(LB1, LB2, out);
}

// round 5
// speedup vs baseline: 1.5413x; 1.4003x over previous
#include <cuda_runtime.h>
#include <cuda_fp16.h>
#include <cstdint>

// ============================================================================
// InteractAttention on sm_103 (base target):
//   conv: activations fp32 -> fp16       wpack: weights -> packed half2 pairs
//   6 GEMMs via mma.sync.m16n8k16.f16 (fp32 accum) -> fp32 scratch -> epilogue
//   g=0: xc@LW1  g=1: xc@AW12  g=2: xc@AW2  g=3: xp@LW2  g=4: xp@AW1  g=5: xp@AW23
// ============================================================================

#define B_ROWS   32768
#define H_DIM    256
#define MT       128
#define KCH      32                    // K chunk (32 halves = 16 half2)
#define STAGES   6
#define NTHREADS 512
#define N_ROW_TILES (B_ROWS / MT)      // 256
#define SCRATCH_PER 8388608ull

__device__ float  g_scratch[6ull * SCRATCH_PER];
__device__ __half g_xch[32768ull * 768];
__device__ __half g_xph[32768ull * 2048];
__device__ __half2 g_wp[1081344];      // packed weights: (W[2k][n], W[2k+1][n])

// half2 offsets of each packed weight matrix (K/2 * 256 each)
#define WP0 0u         // LW1  384x256
#define WP1 98304u     // AW12
#define WP2 196608u    // AW2
#define WP3 294912u    // LW2  1024x256
#define WP4 557056u    // AW1
#define WP5 819200u    // AW23

// smem strides (4B words = half2 units), conflict-free fragment reads
#define A_STRIDE2 20                   // bank = 20*g8 + tg : 32 distinct
#define B_STRIDE2 264                  // bank = 8*tg + g8  : 32 distinct
#define A_BYTES   (MT * A_STRIDE2 * 4)          // 10240
#define B_BYTES   (16 * B_STRIDE2 * 4)          // 16896
#define STAGE_BYTES (A_BYTES + B_BYTES)         // 27136
#define SMEM_BYTES  (STAGES * STAGE_BYTES)      // 162816

__device__ __forceinline__ uint32_t smem_u32(const void* p) {
    uint32_t a;
    asm("{ .reg .u64 t; cvta.to.shared.u64 t, %1; cvt.u32.u64 %0, t; }"
        : "=r"(a) : "l"(p));
    return a;
}
__device__ __forceinline__ void cp16(uint32_t dst, const void* src) {
    asm volatile("cp.async.cg.shared.global [%0], [%1], 16;" :: "r"(dst), "l"(src));
}
__device__ __forceinline__ void mma_f16(float* c, const uint32_t* a, const uint32_t* b) {
    asm volatile(
        "mma.sync.aligned.m16n8k16.row.col.f32.f16.f16.f32 "
        "{%0,%1,%2,%3}, {%4,%5,%6,%7}, {%8,%9}, {%0,%1,%2,%3};"
        : "+f"(c[0]), "+f"(c[1]), "+f"(c[2]), "+f"(c[3])
        : "r"(a[0]), "r"(a[1]), "r"(a[2]), "r"(a[3]), "r"(b[0]), "r"(b[1]));
}

// ---------------- activation conversion: fp32 -> fp16 ----------------
// 23,068,672 float4 total (xc: 6,291,456 then xp)
__global__ void __launch_bounds__(512)
conv_kernel(const float* __restrict__ xc, const float* __restrict__ xp) {
    const unsigned f = blockIdx.x * 512u + threadIdx.x;
    const float4* src; uint2* dst; unsigned off;
    if (f < 6291456u) { src = (const float4*)xc; dst = (uint2*)g_xch; off = f; }
    else { src = (const float4*)xp; dst = (uint2*)g_xph; off = f - 6291456u; }
    float4 v = src[off];
    __half2 h01 = __floats2half2_rn(v.x, v.y);
    __half2 h23 = __floats2half2_rn(v.z, v.w);
    uint2 o;
    o.x = *reinterpret_cast<uint32_t*>(&h01);
    o.y = *reinterpret_cast<uint32_t*>(&h23);
    dst[off] = o;
}

// ---------------- weight packing: fp32 [K][256] -> half2 [K/2][256] --------
// 270,336 uint4 outputs (4 half2 = 4 columns each)
__global__ void __launch_bounds__(512)
wpack_kernel(const float* __restrict__ s0, const float* __restrict__ s1,
             const float* __restrict__ s2, const float* __restrict__ s3,
             const float* __restrict__ s4, const float* __restrict__ s5) {
    const unsigned f = blockIdx.x * 512u + threadIdx.x;   // uint4 index
    if (f >= 270336u) return;
    const float* src; unsigned off;
    if      (f <  24576u) { src = s0; off = f; }
    else if (f <  49152u) { src = s1; off = f -  24576u; }
    else if (f <  73728u) { src = s2; off = f -  49152u; }
    else if (f < 139264u) { src = s3; off = f -  73728u; }
    else if (f < 204800u) { src = s4; off = f - 139264u; }
    else                  { src = s5; off = f - 204800u; }
    const unsigned k2 = off >> 6;        // 64 uint4 per k2-row
    const unsigned n4 = off & 63;
    float4 r0 = ((const float4*)src)[(2 * k2) * 64 + n4];
    float4 r1 = ((const float4*)src)[(2 * k2 + 1) * 64 + n4];
    __half2 h0 = __floats2half2_rn(r0.x, r1.x);
    __half2 h1 = __floats2half2_rn(r0.y, r1.y);
    __half2 h2 = __floats2half2_rn(r0.z, r1.z);
    __half2 h3 = __floats2half2_rn(r0.w, r1.w);
    uint4 o;
    o.x = *reinterpret_cast<uint32_t*>(&h0);
    o.y = *reinterpret_cast<uint32_t*>(&h1);
    o.z = *reinterpret_cast<uint32_t*>(&h2);
    o.w = *reinterpret_cast<uint32_t*>(&h3);
    ((uint4*)g_wp)[f] = o;
}

// ---------------- GEMM ----------------
__global__ void __launch_bounds__(NTHREADS, 1)
gemm_f16_kernel() {
    extern __shared__ float smem[];
    const int tid = threadIdx.x;
    const int wid = tid >> 5;
    const int lid = tid & 31;
    const int g8  = lid >> 2;          // 0..7
    const int tg  = lid & 3;           // 0..3
    const int wm  = wid & 3;           // rows wm*32..+31
    const int wn  = wid >> 2;          // cols wn*64..+63

    // pic (K=2048) CTAs first; 3 same-tile CTAs adjacent for L2 A-sharing
    const int bid = blockIdx.x;
    int g, tile;
    if (bid < 3 * N_ROW_TILES) { tile = bid / 3; g = 3 + bid % 3; }
    else { const int b2 = bid - 3 * N_ROW_TILES; tile = b2 / 3; g = b2 % 3; }

    const __half* X; const __half2* W; int K;
    if      (g == 0) { X = g_xch; W = g_wp + WP0; K = 768;  }
    else if (g == 1) { X = g_xch; W = g_wp + WP1; K = 768;  }
    else if (g == 2) { X = g_xch; W = g_wp + WP2; K = 768;  }
    else if (g == 3) { X = g_xph; W = g_wp + WP3; K = 2048; }
    else if (g == 4) { X = g_xph; W = g_wp + WP4; K = 2048; }
    else             { X = g_xph; W = g_wp + WP5; K = 2048; }

    const __half* Xb = X + (size_t)tile * MT * K;
    float* Y = g_scratch + (size_t)g * SCRATCH_PER + (size_t)tile * (MT * H_DIM);

    const uint32_t sb = smem_u32(smem);
    const int NK = K >> 5;             // 24 or 64 chunks

    float c[2][8][4];
    #pragma unroll
    for (int mt = 0; mt < 2; mt++)
        #pragma unroll
        for (int nt = 0; nt < 8; nt++)
            #pragma unroll
            for (int r = 0; r < 4; r++) c[mt][nt][r] = 0.0f;

    // stage loader: A 512 cp16 (1/thread) + B 1024 cp16 (2/thread)
    auto load_stage = [&](int chunk) {
        const int st = chunk % STAGES;
        const uint32_t stA = sb + st * STAGE_BYTES;
        const uint32_t stB = stA + A_BYTES;
        const int kc  = chunk * KCH;       // half offset into A rows
        const int kc2 = chunk * 16;        // half2-row offset into W
        {   // A: 128 rows x 4 vec16 (8 halves each)
            const int row = tid >> 2;
            const int v   = tid & 3;
            cp16(stA + row * (A_STRIDE2 * 4) + v * 16,
                 Xb + (size_t)row * K + kc + v * 8);
        }
        #pragma unroll
        for (int i = 0; i < 2; i++) {      // B: 16 k2-rows x 64 vec16
            const int f  = tid + i * NTHREADS;
            const int k2 = f >> 6;
            const int v  = f & 63;
            cp16(stB + k2 * (B_STRIDE2 * 4) + v * 16,
                 W + (size_t)(kc2 + k2) * 256 + v * 4);
        }
        asm volatile("cp.async.commit_group;" ::: "memory");
    };

    #pragma unroll
    for (int s = 0; s < STAGES - 1; s++) load_stage(s);

    for (int i = 0; i < NK; i++) {
        asm volatile("cp.async.wait_group %0;" :: "n"(STAGES - 2) : "memory");
        __syncthreads();
        // safe: stage (i+STAGES-1)%STAGES == (i-1)%STAGES, compute(i-1) is done
        if (i + STAGES - 1 < NK) load_stage(i + STAGES - 1);

        const int st = i % STAGES;
        const uint32_t* As = (const uint32_t*)smem + st * (STAGE_BYTES / 4);
        const uint32_t* Bs = As + (A_BYTES / 4);

        #pragma unroll
        for (int step = 0; step < 2; step++) {     // two k16 per chunk
            const int k2b = step * 8;
            uint32_t b[8][2];
            #pragma unroll
            for (int nt = 0; nt < 8; nt++) {
                const int n = wn * 64 + nt * 8 + g8;
                b[nt][0] = Bs[(k2b + tg) * B_STRIDE2 + n];
                b[nt][1] = Bs[(k2b + tg + 4) * B_STRIDE2 + n];
            }
            uint32_t a[2][4];
            #pragma unroll
            for (int mt = 0; mt < 2; mt++) {
                const int r0 = wm * 32 + mt * 16 + g8;
                a[mt][0] = As[r0 * A_STRIDE2 + k2b + tg];
                a[mt][1] = As[(r0 + 8) * A_STRIDE2 + k2b + tg];
                a[mt][2] = As[r0 * A_STRIDE2 + k2b + tg + 4];
                a[mt][3] = As[(r0 + 8) * A_STRIDE2 + k2b + tg + 4];
            }
            #pragma unroll
            for (int mt = 0; mt < 2; mt++)
                #pragma unroll
                for (int nt = 0; nt < 8; nt++)
                    mma_f16(c[mt][nt], a[mt], b[nt]);
        }
    }

    #pragma unroll
    for (int mt = 0; mt < 2; mt++) {
        const int r0 = wm * 32 + mt * 16 + g8;
        #pragma unroll
        for (int nt = 0; nt < 8; nt++) {
            const int col = wn * 64 + nt * 8 + tg * 2;
            *(float2*)(Y + (size_t)r0 * H_DIM + col) =
                make_float2(c[mt][nt][0], c[mt][nt][1]);
            *(float2*)(Y + (size_t)(r0 + 8) * H_DIM + col) =
                make_float2(c[mt][nt][2], c[mt][nt][3]);
        }
    }
}

// ---------------- epilogue: one warp per row ----------------
__device__ __forceinline__ float wsum(float v) {
    #pragma unroll
    for (int o = 16; o; o >>= 1) v += __shfl_xor_sync(0xFFFFFFFFu, v, o);
    return v;
}
__device__ __forceinline__ void load8(float* a, const float* base, int lane) {
    const float4* p = (const float4*)base;
    float4 x = p[lane], y = p[lane + 32];
    a[0]=x.x; a[1]=x.y; a[2]=x.z; a[3]=x.w;
    a[4]=y.x; a[5]=y.y; a[6]=y.z; a[7]=y.w;
}
__device__ __forceinline__ void store8(float* base, const float* a, int lane) {
    float4* p = (float4*)base;
    p[lane]      = make_float4(a[0], a[1], a[2], a[3]);
    p[lane + 32] = make_float4(a[4], a[5], a[6], a[7]);
}
__device__ __forceinline__ float sigm(float x) {
    return 1.0f / (1.0f + __expf(-x));
}
__device__ __forceinline__ float tanh_fast(float x) {
    return 1.0f - 2.0f / (1.0f + __expf(2.0f * x));
}

__global__ void __launch_bounds__(256)
epilogue_kernel(const float* __restrict__ lb1, const float* __restrict__ lb2,
                float* __restrict__ out) {
    const int lane = threadIdx.x & 31;
    const int row  = blockIdx.x * 8 + (threadIdx.x >> 5);
    const size_t off = (size_t)row * H_DIM;

    const float* S0 = g_scratch + 0 * SCRATCH_PER + off;
    const float* S1 = g_scratch + 1 * SCRATCH_PER + off;
    const float* S2 = g_scratch + 2 * SCRATCH_PER + off;
    const float* S3 = g_scratch + 3 * SCRATCH_PER + off;
    const float* S4 = g_scratch + 4 * SCRATCH_PER + off;
    const float* S5 = g_scratch + 5 * SCRATCH_PER + off;

    float cb[8], a12[8], a2[8], pb[8], a1[8], a23[8], b1[8], b2[8];
    load8(cb, S0, lane);  load8(a12, S1, lane); load8(a2, S2, lane);
    load8(pb, S3, lane);  load8(a1, S4, lane);  load8(a23, S5, lane);
    load8(b1, lb1, lane); load8(b2, lb2, lane);

    float s_cw = 0.f, s_pw1 = 0.f, s_num = 0.f, s_cc = 0.f, s_pp = 0.f;
    float pwv[8], cw1[8];
    #pragma unroll
    for (int j = 0; j < 8; j++) {
        cb[j] += b1[j];
        pb[j] += b2[j];
        pwv[j] = pb[j] * sigm(a1[j]);
        cw1[j] = cb[j] * sigm(a2[j]);
        s_cw  += cb[j] * sigm(a12[j]);
        s_pw1 += pb[j] * sigm(a23[j]);
        s_num += cb[j] * pb[j];
        s_cc  += cb[j] * cb[j];
        s_pp  += pb[j] * pb[j];
    }
    s_cw  = wsum(s_cw)  * (1.0f / 256.0f);
    s_pw1 = wsum(s_pw1) * (1.0f / 256.0f);
    s_num = wsum(s_num);
    s_cc  = wsum(s_cc);
    s_pp  = wsum(s_pp);
    const float sim = s_num / (sqrtf(s_cc) * sqrtf(s_pp));

    float co[8], po[8];
    #pragma unroll
    for (int j = 0; j < 8; j++) {
        co[j] = sigm(cb[j]) * tanh_fast(pwv[j] * s_cw);
        po[j] = sigm(pb[j]) * tanh_fast(cw1[j] * s_pw1) * sim;
    }
    store8(out + off, co, lane);
    store8(out + (size_t)B_ROWS * H_DIM + off, po, lane);
}

// ---------------- launch ----------------
extern "C" void kernel_launch(void* const* d_in, const int* in_sizes, int n_in,
                              void* d_out, int out_size) {
    const float* xc  = (const float*)d_in[0];
    const float* xp  = (const float*)d_in[1];
    const float* LW1 = (const float*)d_in[2];
    const float* LB1 = (const float*)d_in[3];
    const float* LW2 = (const float*)d_in[4];
    const float* LB2 = (const float*)d_in[5];
    const float* AW1 = (const float*)d_in[6];
    const float* AW12= (const float*)d_in[7];
    const float* AW2 = (const float*)d_in[8];
    const float* AW23= (const float*)d_in[9];
    float* out = (float*)d_out;

    conv_kernel<<<45056, 512>>>(xc, xp);
    wpack_kernel<<<528, 512>>>(LW1, AW12, AW2, LW2, AW1, AW23);

    cudaFuncSetAttribute(gemm_f16_kernel,
                         cudaFuncAttributeMaxDynamicSharedMemorySize, SMEM_BYTES);
    gemm_f16_kernel<<<N_ROW_TILES * 6, NTHREADS, SMEM_BYTES>>>();

    epilogue_kernel<<<B_ROWS / 8, 256>>>(LB1, LB2, out);
}

// round 6
// speedup vs baseline: 1.6611x; 1.0777x over previous
#include <cuda_runtime.h>
#include <cuda_fp16.h>
#include <cstdint>

// ============================================================================
// InteractAttention on sm_103 (base target):
//   wpack: weights fp32 -> packed half2 pairs (k-adjacent)
//   GEMM: fp32 A via cp.async, fragment-time cvt to half2, mma.m16n8k16.f16
//         -> cb/pb scratch fp32, gate scratch fp16
//   epilogue: fused row reductions -> out
//   g=0: xc@LW1  g=1: xc@AW12  g=2: xc@AW2  g=3: xp@LW2  g=4: xp@AW1  g=5: xp@AW23
// ============================================================================

#define B_ROWS   32768
#define H_DIM    256
#define MT       128
#define KCH      32                    // K chunk (32 halves / 32 floats)
#define STAGES   5
#define NTHREADS 512
#define N_ROW_TILES (B_ROWS / MT)      // 256
#define SCRATCH_PER 8388608ull         // B_ROWS * H_DIM

__device__ float  g_sf[2ull * SCRATCH_PER];   // 0: cb (g0), 1: pb (g3)
__device__ __half g_sh[4ull * SCRATCH_PER];   // 0:a12(g1) 1:a2(g2) 2:a1(g4) 3:a23(g5)
__device__ __half2 g_wp[1081344];      // packed weights: (W[2k][n], W[2k+1][n])

// half2 offsets of each packed weight matrix (K/2 * 256 each)
#define WP0 0u         // LW1  384x256
#define WP1 98304u     // AW12
#define WP2 196608u    // AW2
#define WP3 294912u    // LW2  1024x256
#define WP4 557056u    // AW1
#define WP5 819200u    // AW23

// smem layout (word = 4B)
// A: fp32, 128 rows x 40-word stride (32 data + 8 pad) -> LDS.64 pair-bank 4*g8+tg
// B: half2, 16 k2-rows x 264-word stride               -> bank 8*tg+g8
#define A_STRIDE_W 40
#define B_STRIDE2  264
#define A_BYTES   (MT * A_STRIDE_W * 4)         // 20480
#define B_BYTES   (16 * B_STRIDE2 * 4)          // 16896
#define STAGE_BYTES (A_BYTES + B_BYTES)         // 37376
#define STAGE_WORDS (STAGE_BYTES / 4)           // 9344
#define SMEM_BYTES  (STAGES * STAGE_BYTES)      // 186880

__device__ __forceinline__ uint32_t smem_u32(const void* p) {
    uint32_t a;
    asm("{ .reg .u64 t; cvta.to.shared.u64 t, %1; cvt.u32.u64 %0, t; }"
        : "=r"(a) : "l"(p));
    return a;
}
__device__ __forceinline__ void cp16(uint32_t dst, const void* src) {
    asm volatile("cp.async.cg.shared.global [%0], [%1], 16;" :: "r"(dst), "l"(src));
}
__device__ __forceinline__ void mma_f16(float* c, const uint32_t* a, const uint32_t* b) {
    asm volatile(
        "mma.sync.aligned.m16n8k16.row.col.f32.f16.f16.f32 "
        "{%0,%1,%2,%3}, {%4,%5,%6,%7}, {%8,%9}, {%0,%1,%2,%3};"
        : "+f"(c[0]), "+f"(c[1]), "+f"(c[2]), "+f"(c[3])
        : "r"(a[0]), "r"(a[1]), "r"(a[2]), "r"(a[3]), "r"(b[0]), "r"(b[1]));
}
__device__ __forceinline__ uint32_t pack_h2(float lo, float hi) {
    __half2 h = __floats2half2_rn(lo, hi);
    return *reinterpret_cast<uint32_t*>(&h);
}

// ---------------- weight packing: fp32 [K][256] -> half2 [K/2][256] --------
__global__ void __launch_bounds__(512)
wpack_kernel(const float* __restrict__ s0, const float* __restrict__ s1,
             const float* __restrict__ s2, const float* __restrict__ s3,
             const float* __restrict__ s4, const float* __restrict__ s5) {
    const unsigned f = blockIdx.x * 512u + threadIdx.x;   // uint4 index
    if (f >= 270336u) return;
    const float* src; unsigned off;
    if      (f <  24576u) { src = s0; off = f; }
    else if (f <  49152u) { src = s1; off = f -  24576u; }
    else if (f <  73728u) { src = s2; off = f -  49152u; }
    else if (f < 139264u) { src = s3; off = f -  73728u; }
    else if (f < 204800u) { src = s4; off = f - 139264u; }
    else                  { src = s5; off = f - 204800u; }
    const unsigned k2 = off >> 6;        // 64 uint4 per k2-row
    const unsigned n4 = off & 63;
    float4 r0 = ((const float4*)src)[(2 * k2) * 64 + n4];
    float4 r1 = ((const float4*)src)[(2 * k2 + 1) * 64 + n4];
    uint4 o;
    o.x = pack_h2(r0.x, r1.x);
    o.y = pack_h2(r0.y, r1.y);
    o.z = pack_h2(r0.z, r1.z);
    o.w = pack_h2(r0.w, r1.w);
    ((uint4*)g_wp)[f] = o;
}

// ---------------- GEMM ----------------
__global__ void __launch_bounds__(NTHREADS, 1)
gemm_f16_kernel(const float* __restrict__ xc, const float* __restrict__ xp) {
    extern __shared__ float smem[];
    const int tid = threadIdx.x;
    const int wid = tid >> 5;
    const int lid = tid & 31;
    const int g8  = lid >> 2;          // 0..7
    const int tg  = lid & 3;           // 0..3
    const int wm  = wid & 3;           // rows wm*32..+31
    const int wn  = wid >> 2;          // cols wn*64..+63

    // pic (K=2048) CTAs first; 3 same-tile CTAs adjacent for L2 A-sharing
    const int bid = blockIdx.x;
    int g, tile;
    if (bid < 3 * N_ROW_TILES) { tile = bid / 3; g = 3 + bid % 3; }
    else { const int b2 = bid - 3 * N_ROW_TILES; tile = b2 / 3; g = b2 % 3; }

    const float* X; const __half2* W; int K;
    if      (g == 0) { X = xc; W = g_wp + WP0; K = 768;  }
    else if (g == 1) { X = xc; W = g_wp + WP1; K = 768;  }
    else if (g == 2) { X = xc; W = g_wp + WP2; K = 768;  }
    else if (g == 3) { X = xp; W = g_wp + WP3; K = 2048; }
    else if (g == 4) { X = xp; W = g_wp + WP4; K = 2048; }
    else             { X = xp; W = g_wp + WP5; K = 2048; }

    const float* Xb = X + (size_t)tile * MT * K;

    const uint32_t sb = smem_u32(smem);
    const int NK = K >> 5;             // 24 or 64 chunks

    float c[2][8][4];
    #pragma unroll
    for (int mt = 0; mt < 2; mt++)
        #pragma unroll
        for (int nt = 0; nt < 8; nt++)
            #pragma unroll
            for (int r = 0; r < 4; r++) c[mt][nt][r] = 0.0f;

    // stage loader: A 1024 cp16 fp32 (2/thread) + B 1024 cp16 (2/thread)
    auto load_stage = [&](int chunk) {
        const int st = chunk % STAGES;
        const uint32_t stA = sb + st * STAGE_BYTES;
        const uint32_t stB = stA + A_BYTES;
        const int kc  = chunk * KCH;       // float offset into A rows
        const int kc2 = chunk * 16;        // half2-row offset into W
        #pragma unroll
        for (int i = 0; i < 2; i++) {      // A: 128 rows x 8 vec16 (4 floats)
            const int f   = tid + i * NTHREADS;
            const int row = f >> 3;
            const int v   = f & 7;
            cp16(stA + row * (A_STRIDE_W * 4) + v * 16,
                 Xb + (size_t)row * K + kc + v * 4);
        }
        #pragma unroll
        for (int i = 0; i < 2; i++) {      // B: 16 k2-rows x 64 vec16
            const int f  = tid + i * NTHREADS;
            const int k2 = f >> 6;
            const int v  = f & 63;
            cp16(stB + k2 * (B_STRIDE2 * 4) + v * 16,
                 W + (size_t)(kc2 + k2) * 256 + v * 4);
        }
        asm volatile("cp.async.commit_group;" ::: "memory");
    };

    #pragma unroll
    for (int s = 0; s < STAGES - 1; s++) load_stage(s);

    for (int i = 0; i < NK; i++) {
        asm volatile("cp.async.wait_group %0;" :: "n"(STAGES - 2) : "memory");
        __syncthreads();
        // safe: stage (i+STAGES-1)%STAGES == (i-1)%STAGES, compute(i-1) is done
        if (i + STAGES - 1 < NK) load_stage(i + STAGES - 1);

        const int st = i % STAGES;
        const float*    As = smem + st * STAGE_WORDS;
        const uint32_t* Bs = (const uint32_t*)(As + A_BYTES / 4);

        #pragma unroll
        for (int step = 0; step < 2; step++) {     // two k16 per chunk
            const int k2b = step * 8;
            uint32_t b[8][2];
            #pragma unroll
            for (int nt = 0; nt < 8; nt++) {
                const int n = wn * 64 + nt * 8 + g8;
                b[nt][0] = Bs[(k2b + tg) * B_STRIDE2 + n];
                b[nt][1] = Bs[(k2b + tg + 4) * B_STRIDE2 + n];
            }
            uint32_t a[2][4];
            #pragma unroll
            for (int mt = 0; mt < 2; mt++) {
                const int r0 = wm * 32 + mt * 16 + g8;
                float2 v0 = *(const float2*)(As + r0 * A_STRIDE_W + 2 * (k2b + tg));
                float2 v1 = *(const float2*)(As + (r0 + 8) * A_STRIDE_W + 2 * (k2b + tg));
                float2 v2 = *(const float2*)(As + r0 * A_STRIDE_W + 2 * (k2b + tg + 4));
                float2 v3 = *(const float2*)(As + (r0 + 8) * A_STRIDE_W + 2 * (k2b + tg + 4));
                a[mt][0] = pack_h2(v0.x, v0.y);
                a[mt][1] = pack_h2(v1.x, v1.y);
                a[mt][2] = pack_h2(v2.x, v2.y);
                a[mt][3] = pack_h2(v3.x, v3.y);
            }
            #pragma unroll
            for (int mt = 0; mt < 2; mt++)
                #pragma unroll
                for (int nt = 0; nt < 8; nt++)
                    mma_f16(c[mt][nt], a[mt], b[nt]);
        }
    }

    // ---- writeback ----
    if (g == 0 || g == 3) {
        float* Yf = g_sf + (size_t)(g == 0 ? 0 : 1) * SCRATCH_PER
                         + (size_t)tile * (MT * H_DIM);
        #pragma unroll
        for (int mt = 0; mt < 2; mt++) {
            const int r0 = wm * 32 + mt * 16 + g8;
            #pragma unroll
            for (int nt = 0; nt < 8; nt++) {
                const int col = wn * 64 + nt * 8 + tg * 2;
                *(float2*)(Yf + (size_t)r0 * H_DIM + col) =
                    make_float2(c[mt][nt][0], c[mt][nt][1]);
                *(float2*)(Yf + (size_t)(r0 + 8) * H_DIM + col) =
                    make_float2(c[mt][nt][2], c[mt][nt][3]);
            }
        }
    } else {
        const int idx = (g == 1) ? 0 : (g == 2) ? 1 : (g == 4) ? 2 : 3;
        __half* Yh = g_sh + (size_t)idx * SCRATCH_PER
                          + (size_t)tile * (MT * H_DIM);
        #pragma unroll
        for (int mt = 0; mt < 2; mt++) {
            const int r0 = wm * 32 + mt * 16 + g8;
            #pragma unroll
            for (int nt = 0; nt < 8; nt++) {
                const int col = wn * 64 + nt * 8 + tg * 2;
                *(uint32_t*)(Yh + (size_t)r0 * H_DIM + col) =
                    pack_h2(c[mt][nt][0], c[mt][nt][1]);
                *(uint32_t*)(Yh + (size_t)(r0 + 8) * H_DIM + col) =
                    pack_h2(c[mt][nt][2], c[mt][nt][3]);
            }
        }
    }
}

// ---------------- epilogue: one warp per row ----------------
__device__ __forceinline__ float wsum(float v) {
    #pragma unroll
    for (int o = 16; o; o >>= 1) v += __shfl_xor_sync(0xFFFFFFFFu, v, o);
    return v;
}
__device__ __forceinline__ void load8(float* a, const float* base, int lane) {
    const float4* p = (const float4*)base;
    float4 x = p[lane], y = p[lane + 32];
    a[0]=x.x; a[1]=x.y; a[2]=x.z; a[3]=x.w;
    a[4]=y.x; a[5]=y.y; a[6]=y.z; a[7]=y.w;
}
__device__ __forceinline__ void load8h(float* a, const __half* base, int lane) {
    const uint2* p = (const uint2*)base;
    uint2 x = p[lane], y = p[lane + 32];
    float2 f;
    f = __half22float2(*(__half2*)&x.x); a[0]=f.x; a[1]=f.y;
    f = __half22float2(*(__half2*)&x.y); a[2]=f.x; a[3]=f.y;
    f = __half22float2(*(__half2*)&y.x); a[4]=f.x; a[5]=f.y;
    f = __half22float2(*(__half2*)&y.y); a[6]=f.x; a[7]=f.y;
}
__device__ __forceinline__ void store8(float* base, const float* a, int lane) {
    float4* p = (float4*)base;
    p[lane]      = make_float4(a[0], a[1], a[2], a[3]);
    p[lane + 32] = make_float4(a[4], a[5], a[6], a[7]);
}
__device__ __forceinline__ float sigm(float x) {
    return 1.0f / (1.0f + __expf(-x));
}
__device__ __forceinline__ float tanh_fast(float x) {
    return 1.0f - 2.0f / (1.0f + __expf(2.0f * x));
}

__global__ void __launch_bounds__(256)
epilogue_kernel(const float* __restrict__ lb1, const float* __restrict__ lb2,
                float* __restrict__ out) {
    const int lane = threadIdx.x & 31;
    const int row  = blockIdx.x * 8 + (threadIdx.x >> 5);
    const size_t off = (size_t)row * H_DIM;

    float cb[8], a12[8], a2[8], pb[8], a1[8], a23[8], b1[8], b2[8];
    load8 (cb,  g_sf + 0 * SCRATCH_PER + off, lane);
    load8 (pb,  g_sf + 1 * SCRATCH_PER + off, lane);
    load8h(a12, g_sh + 0 * SCRATCH_PER + off, lane);
    load8h(a2,  g_sh + 1 * SCRATCH_PER + off, lane);
    load8h(a1,  g_sh + 2 * SCRATCH_PER + off, lane);
    load8h(a23, g_sh + 3 * SCRATCH_PER + off, lane);
    load8 (b1, lb1, lane);
    load8 (b2, lb2, lane);

    float s_cw = 0.f, s_pw1 = 0.f, s_num = 0.f, s_cc = 0.f, s_pp = 0.f;
    float pwv[8], cw1[8];
    #pragma unroll
    for (int j = 0; j < 8; j++) {
        cb[j] += b1[j];
        pb[j] += b2[j];
        pwv[j] = pb[j] * sigm(a1[j]);
        cw1[j] = cb[j] * sigm(a2[j]);
        s_cw  += cb[j] * sigm(a12[j]);
        s_pw1 += pb[j] * sigm(a23[j]);
        s_num += cb[j] * pb[j];
        s_cc  += cb[j] * cb[j];
        s_pp  += pb[j] * pb[j];
    }
    s_cw  = wsum(s_cw)  * (1.0f / 256.0f);
    s_pw1 = wsum(s_pw1) * (1.0f / 256.0f);
    s_num = wsum(s_num);
    s_cc  = wsum(s_cc);
    s_pp  = wsum(s_pp);
    const float sim = s_num / (sqrtf(s_cc) * sqrtf(s_pp));

    float co[8], po[8];
    #pragma unroll
    for (int j = 0; j < 8; j++) {
        co[j] = sigm(cb[j]) * tanh_fast(pwv[j] * s_cw);
        po[j] = sigm(pb[j]) * tanh_fast(cw1[j] * s_pw1) * sim;
    }
    store8(out + off, co, lane);
    store8(out + (size_t)B_ROWS * H_DIM + off, po, lane);
}

// ---------------- launch ----------------
extern "C" void kernel_launch(void* const* d_in, const int* in_sizes, int n_in,
                              void* d_out, int out_size) {
    const float* xc  = (const float*)d_in[0];
    const float* xp  = (const float*)d_in[1];
    const float* LW1 = (const float*)d_in[2];
    const float* LB1 = (const float*)d_in[3];
    const float* LW2 = (const float*)d_in[4];
    const float* LB2 = (const float*)d_in[5];
    const float* AW1 = (const float*)d_in[6];
    const float* AW12= (const float*)d_in[7];
    const float* AW2 = (const float*)d_in[8];
    const float* AW23= (const float*)d_in[9];
    float* out = (float*)d_out;

    wpack_kernel<<<528, 512>>>(LW1, AW12, AW2, LW2, AW1, AW23);

    cudaFuncSetAttribute(gemm_f16_kernel,
                         cudaFuncAttributeMaxDynamicSharedMemorySize, SMEM_BYTES);
    gemm_f16_kernel<<<N_ROW_TILES * 6, NTHREADS, SMEM_BYTES>>>(xc, xp);

    epilogue_kernel<<<B_ROWS / 8, 256>>>(LB1, LB2, out);
}

// round 9
// speedup vs baseline: 1.6616x; 1.0003x over previous
#include <cuda_runtime.h>
#include <cuda_fp16.h>
#include <cstdint>

// ============================================================================
// InteractAttention on sm_103 (base target):
//   wpack: weights fp32 [K][256] -> fp16 n-major [256][K]  (L2-resident, 4.3MB)
//   GEMM: A inline LDG(fp32)->cvt->STS fp16, SW128-swizzled smem both operands,
//         mma.m16n8k16.f16 fp32-accum, K-chunk 64, 4-stage cp.async(B) pipeline
//   scratch: cb/pb fp32, gate pre-activations fp16
//   epilogue: fused row reductions
//   g=0: xc@LW1  g=1: xc@AW12  g=2: xc@AW2  g=3: xp@LW2  g=4: xp@AW1  g=5: xp@AW23
// ============================================================================

#define B_ROWS   32768
#define H_DIM    256
#define MT       128
#define KCH      64                     // K chunk (64 halves = 128B rows)
#define STAGES   4
#define NTHREADS 512
#define N_ROW_TILES (B_ROWS / MT)       // 256
#define SCRATCH_PER 8388608ull

__device__ __align__(16) float  g_sf[2ull * SCRATCH_PER];  // 0: cb (g0), 1: pb (g3)
__device__ __align__(16) __half g_sh[4ull * SCRATCH_PER];  // 0:a12 1:a2 2:a1 3:a23
__device__ __align__(16) __half g_wph[2162688];            // n-major fp16 weights

// half offsets of each weight matrix [256][K]
#define WH0 0u          // LW1  K=768
#define WH1 196608u     // AW12
#define WH2 393216u     // AW2
#define WH3 589824u     // LW2  K=2048
#define WH4 1114112u    // AW1
#define WH5 1638400u    // AW23

// stage: A 128 rows x 128B (16KB) then B 256 rows x 128B (32KB)
#define A_STAGE_BYTES 16384
#define STAGE_BYTES   49152
#define STAGE_WORDS   12288
#define SMEM_BYTES    (STAGES * STAGE_BYTES)   // 196608

// word index of half2 #k2 (0..31) in swizzled 128B row `row`
#define SWW(row, k2) ((row) * 32 + 4 * ((((k2) >> 2)) ^ ((row) & 7)) + ((k2) & 3))

__device__ __forceinline__ uint32_t smem_u32(const void* p) {
    uint32_t a;
    asm("{ .reg .u64 t; cvta.to.shared.u64 t, %1; cvt.u32.u64 %0, t; }"
        : "=r"(a) : "l"(p));
    return a;
}
__device__ __forceinline__ void cp16(uint32_t dst, const void* src) {
    asm volatile("cp.async.cg.shared.global [%0], [%1], 16;" :: "r"(dst), "l"(src));
}
__device__ __forceinline__ void mma_f16(float* c, const uint32_t* a, const uint32_t* b) {
    asm volatile(
        "mma.sync.aligned.m16n8k16.row.col.f32.f16.f16.f32 "
        "{%0,%1,%2,%3}, {%4,%5,%6,%7}, {%8,%9}, {%0,%1,%2,%3};"
        : "+f"(c[0]), "+f"(c[1]), "+f"(c[2]), "+f"(c[3])
        : "r"(a[0]), "r"(a[1]), "r"(a[2]), "r"(a[3]), "r"(b[0]), "r"(b[1]));
}
__device__ __forceinline__ uint32_t pack_h2(float lo, float hi) {
    __half2 h = __floats2half2_rn(lo, hi);
    return *reinterpret_cast<uint32_t*>(&h);
}

// ---------------- weight repack: fp32 [K][256] -> fp16 [256][K] -------------
// one thread per 16B output (8 halves = 8 consecutive k, fixed n); 270336 total
__global__ void __launch_bounds__(512)
wpack_kernel(const float* __restrict__ s0, const float* __restrict__ s1,
             const float* __restrict__ s2, const float* __restrict__ s3,
             const float* __restrict__ s4, const float* __restrict__ s5) {
    const unsigned f = blockIdx.x * 512u + threadIdx.x;
    if (f >= 270336u) return;
    const float* src; unsigned off, K, base;
    if      (f <  24576u) { src = s0; off = f;           K = 768;  base = WH0; }
    else if (f <  49152u) { src = s1; off = f -  24576u; K = 768;  base = WH1; }
    else if (f <  73728u) { src = s2; off = f -  49152u; K = 768;  base = WH2; }
    else if (f < 139264u) { src = s3; off = f -  73728u; K = 2048; base = WH3; }
    else if (f < 204800u) { src = s4; off = f - 139264u; K = 2048; base = WH4; }
    else                  { src = s5; off = f - 204800u; K = 2048; base = WH5; }
    const unsigned kg = K >> 3;            // 16B groups per n-row
    const unsigned n  = off / kg;
    const unsigned k0 = (off % kg) << 3;
    uint4 o;
    o.x = pack_h2(src[(k0 + 0) * 256 + n], src[(k0 + 1) * 256 + n]);
    o.y = pack_h2(src[(k0 + 2) * 256 + n], src[(k0 + 3) * 256 + n]);
    o.z = pack_h2(src[(k0 + 4) * 256 + n], src[(k0 + 5) * 256 + n]);
    o.w = pack_h2(src[(k0 + 6) * 256 + n], src[(k0 + 7) * 256 + n]);
    *(uint4*)(g_wph + base + (size_t)n * K + k0) = o;
}

// ---------------- GEMM ----------------
__global__ void __launch_bounds__(NTHREADS, 1)
gemm_f16_kernel(const float* __restrict__ xc, const float* __restrict__ xp) {
    extern __shared__ float smem[];
    const int tid = threadIdx.x;
    const int wid = tid >> 5;
    const int lid = tid & 31;
    const int g8  = lid >> 2;           // 0..7
    const int tg  = lid & 3;            // 0..3
    const int wm  = wid & 3;            // rows wm*32..+31
    const int wn  = wid >> 2;           // cols wn*64..+63

    // pic (K=2048) CTAs first; 3 same-tile CTAs adjacent for L2 A-sharing
    const int bid = blockIdx.x;
    int g, tile;
    if (bid < 3 * N_ROW_TILES) { tile = bid / 3; g = 3 + bid % 3; }
    else { const int b2 = bid - 3 * N_ROW_TILES; tile = b2 / 3; g = b2 % 3; }

    const float* X; const __half* Wl; int K;
    if      (g == 0) { X = xc; Wl = g_wph + WH0; K = 768;  }
    else if (g == 1) { X = xc; Wl = g_wph + WH1; K = 768;  }
    else if (g == 2) { X = xc; Wl = g_wph + WH2; K = 768;  }
    else if (g == 3) { X = xp; Wl = g_wph + WH3; K = 2048; }
    else if (g == 4) { X = xp; Wl = g_wph + WH4; K = 2048; }
    else             { X = xp; Wl = g_wph + WH5; K = 2048; }

    const float* Xb = X + (size_t)tile * MT * K;
    const uint32_t sb = smem_u32(smem);
    const int NK = K / KCH;             // 12 or 32 chunks

    // per-thread loader coords
    const int am = tid >> 2;            // A row 0..127
    const int acv = tid & 3;            // 16-float group within 64

    float c[2][8][4];
    #pragma unroll
    for (int mt = 0; mt < 2; mt++)
        #pragma unroll
        for (int nt = 0; nt < 8; nt++)
            #pragma unroll
            for (int r = 0; r < 4; r++) c[mt][nt][r] = 0.0f;

    // B loader: 2048 cp16 over 512 threads
    auto load_B = [&](int chunk) {
        const int st = chunk & (STAGES - 1);
        const uint32_t stB = sb + st * STAGE_BYTES + A_STAGE_BYTES;
        const int kc = chunk * KCH;
        #pragma unroll
        for (int j = 0; j < 4; j++) {
            const int f = tid + j * NTHREADS;
            const int n = f >> 3;
            const int v = f & 7;
            cp16(stB + n * 128 + 16 * (v ^ (n & 7)),
                 Wl + (size_t)n * K + kc + v * 8);
        }
        asm volatile("cp.async.commit_group;" ::: "memory");
    };
    // A store: convert 16 floats -> 2 swizzled STS.128
    auto store_A = [&](int chunk, const float4* r) {
        const int st = chunk & (STAGES - 1);
        const uint32_t stA = sb + st * STAGE_BYTES;
        uint4 o0, o1;
        o0.x = pack_h2(r[0].x, r[0].y); o0.y = pack_h2(r[0].z, r[0].w);
        o0.z = pack_h2(r[1].x, r[1].y); o0.w = pack_h2(r[1].z, r[1].w);
        o1.x = pack_h2(r[2].x, r[2].y); o1.y = pack_h2(r[2].z, r[2].w);
        o1.z = pack_h2(r[3].x, r[3].y); o1.w = pack_h2(r[3].z, r[3].w);
        const int c0 = 2 * acv, c1 = 2 * acv + 1;
        *(uint4*)((char*)smem + (stA - sb) + am * 128 + 16 * (c0 ^ (am & 7))) = o0;
        *(uint4*)((char*)smem + (stA - sb) + am * 128 + 16 * (c1 ^ (am & 7))) = o1;
    };
    auto load_A = [&](int chunk, float4* r) {
        const float* src = Xb + (size_t)am * K + chunk * KCH + acv * 16;
        r[0] = *(const float4*)(src + 0);
        r[1] = *(const float4*)(src + 4);
        r[2] = *(const float4*)(src + 8);
        r[3] = *(const float4*)(src + 12);
    };

    // prologue: stages 0..STAGES-2
    #pragma unroll
    for (int s = 0; s < STAGES - 1; s++) {
        float4 r[4];
        load_A(s, r);
        store_A(s, r);
        load_B(s);
    }

    for (int i = 0; i < NK; i++) {
        asm volatile("cp.async.wait_group %0;" :: "n"(STAGES - 2) : "memory");
        __syncthreads();

        const bool pf = (i + STAGES - 1 < NK);
        float4 rA[4];
        if (pf) { load_A(i + STAGES - 1, rA); load_B(i + STAGES - 1); }

        const int st = i & (STAGES - 1);
        const uint32_t* As = (const uint32_t*)smem + st * STAGE_WORDS;
        const uint32_t* Bs = As + (A_STAGE_BYTES / 4);

        #pragma unroll
        for (int s = 0; s < 4; s++) {               // four k16 steps
            const int kl = 8 * s + tg;              // k2 low
            const int kh = kl + 4;                  // k2 high
            uint32_t b[8][2];
            #pragma unroll
            for (int nt = 0; nt < 8; nt++) {
                const int n = wn * 64 + nt * 8 + g8;
                b[nt][0] = Bs[SWW(n, kl)];
                b[nt][1] = Bs[SWW(n, kh)];
            }
            uint32_t a[2][4];
            #pragma unroll
            for (int mt = 0; mt < 2; mt++) {
                const int m = wm * 32 + mt * 16 + g8;
                a[mt][0] = As[SWW(m, kl)];
                a[mt][1] = As[SWW(m + 8, kl)];
                a[mt][2] = As[SWW(m, kh)];
                a[mt][3] = As[SWW(m + 8, kh)];
            }
            #pragma unroll
            for (int mt = 0; mt < 2; mt++)
                #pragma unroll
                for (int nt = 0; nt < 8; nt++)
                    mma_f16(c[mt][nt], a[mt], b[nt]);
        }

        if (pf) store_A(i + STAGES - 1, rA);
    }

    // ---- writeback ----
    if (g == 0 || g == 3) {
        float* Yf = g_sf + (size_t)(g == 0 ? 0 : 1) * SCRATCH_PER
                         + (size_t)tile * (MT * H_DIM);
        #pragma unroll
        for (int mt = 0; mt < 2; mt++) {
            const int r0 = wm * 32 + mt * 16 + g8;
            #pragma unroll
            for (int nt = 0; nt < 8; nt++) {
                const int col = wn * 64 + nt * 8 + tg * 2;
                *(float2*)(Yf + (size_t)r0 * H_DIM + col) =
                    make_float2(c[mt][nt][0], c[mt][nt][1]);
                *(float2*)(Yf + (size_t)(r0 + 8) * H_DIM + col) =
                    make_float2(c[mt][nt][2], c[mt][nt][3]);
            }
        }
    } else {
        const int idx = (g == 1) ? 0 : (g == 2) ? 1 : (g == 4) ? 2 : 3;
        __half* Yh = g_sh + (size_t)idx * SCRATCH_PER
                          + (size_t)tile * (MT * H_DIM);
        #pragma unroll
        for (int mt = 0; mt < 2; mt++) {
            const int r0 = wm * 32 + mt * 16 + g8;
            #pragma unroll
            for (int nt = 0; nt < 8; nt++) {
                const int col = wn * 64 + nt * 8 + tg * 2;
                *(uint32_t*)(Yh + (size_t)r0 * H_DIM + col) =
                    pack_h2(c[mt][nt][0], c[mt][nt][1]);
                *(uint32_t*)(Yh + (size_t)(r0 + 8) * H_DIM + col) =
                    pack_h2(c[mt][nt][2], c[mt][nt][3]);
            }
        }
    }
}

// ---------------- epilogue: one warp per row ----------------
__device__ __forceinline__ float wsum(float v) {
    #pragma unroll
    for (int o = 16; o; o >>= 1) v += __shfl_xor_sync(0xFFFFFFFFu, v, o);
    return v;
}
__device__ __forceinline__ void load8(float* a, const float* base, int lane) {
    const float4* p = (const float4*)base;
    float4 x = p[lane], y = p[lane + 32];
    a[0]=x.x; a[1]=x.y; a[2]=x.z; a[3]=x.w;
    a[4]=y.x; a[5]=y.y; a[6]=y.z; a[7]=y.w;
}
__device__ __forceinline__ void load8h(float* a, const __half* base, int lane) {
    const uint2* p = (const uint2*)base;
    uint2 x = p[lane], y = p[lane + 32];
    float2 f;
    f = __half22float2(*(__half2*)&x.x); a[0]=f.x; a[1]=f.y;
    f = __half22float2(*(__half2*)&x.y); a[2]=f.x; a[3]=f.y;
    f = __half22float2(*(__half2*)&y.x); a[4]=f.x; a[5]=f.y;
    f = __half22float2(*(__half2*)&y.y); a[6]=f.x; a[7]=f.y;
}
__device__ __forceinline__ void store8(float* base, const float* a, int lane) {
    float4* p = (float4*)base;
    p[lane]      = make_float4(a[0], a[1], a[2], a[3]);
    p[lane + 32] = make_float4(a[4], a[5], a[6], a[7]);
}
__device__ __forceinline__ float sigm(float x) { return 1.0f / (1.0f + __expf(-x)); }
__device__ __forceinline__ float tanh_fast(float x) {
    return 1.0f - 2.0f / (1.0f + __expf(2.0f * x));
}

__global__ void __launch_bounds__(256)
epilogue_kernel(const float* __restrict__ lb1, const float* __restrict__ lb2,
                float* __restrict__ out) {
    const int lane = threadIdx.x & 31;
    const int row  = blockIdx.x * 8 + (threadIdx.x >> 5);
    const size_t off = (size_t)row * H_DIM;

    float cb[8], a12[8], a2[8], pb[8], a1[8], a23[8], b1[8], b2[8];
    load8 (cb,  g_sf + 0 * SCRATCH_PER + off, lane);
    load8 (pb,  g_sf + 1 * SCRATCH_PER + off, lane);
    load8h(a12, g_sh + 0 * SCRATCH_PER + off, lane);
    load8h(a2,  g_sh + 1 * SCRATCH_PER + off, lane);
    load8h(a1,  g_sh + 2 * SCRATCH_PER + off, lane);
    load8h(a23, g_sh + 3 * SCRATCH_PER + off, lane);
    load8 (b1, lb1, lane);
    load8 (b2, lb2, lane);

    float s_cw = 0.f, s_pw1 = 0.f, s_num = 0.f, s_cc = 0.f, s_pp = 0.f;
    float pwv[8], cw1[8];
    #pragma unroll
    for (int j = 0; j < 8; j++) {
        cb[j] += b1[j];
        pb[j] += b2[j];
        pwv[j] = pb[j] * sigm(a1[j]);
        cw1[j] = cb[j] * sigm(a2[j]);
        s_cw  += cb[j] * sigm(a12[j]);
        s_pw1 += pb[j] * sigm(a23[j]);
        s_num += cb[j] * pb[j];
        s_cc  += cb[j] * cb[j];
        s_pp  += pb[j] * pb[j];
    }
    s_cw  = wsum(s_cw)  * (1.0f / 256.0f);
    s_pw1 = wsum(s_pw1) * (1.0f / 256.0f);
    s_num = wsum(s_num);
    s_cc  = wsum(s_cc);
    s_pp  = wsum(s_pp);
    const float sim = s_num / (sqrtf(s_cc) * sqrtf(s_pp));

    float co[8], po[8];
    #pragma unroll
    for (int j = 0; j < 8; j++) {
        co[j] = sigm(cb[j]) * tanh_fast(pwv[j] * s_cw);
        po[j] = sigm(pb[j]) * tanh_fast(cw1[j] * s_pw1) * sim;
    }
    store8(out + off, co, lane);
    store8(out + (size_t)B_ROWS * H_DIM + off, po, lane);
}

// ---------------- launch ----------------
extern "C" void kernel_launch(void* const* d_in, const int* in_sizes, int n_in,
                              void* d_out, int out_size) {
    const float* xc  = (const float*)d_in[0];
    const float* xp  = (const float*)d_in[1];
    const float* LW1 = (const float*)d_in[2];
    const float* LB1 = (const float*)d_in[3];
    const float* LW2 = (const float*)d_in[4];
    const float* LB2 = (const float*)d_in[5];
    const float* AW1 = (const float*)d_in[6];
    const float* AW12= (const float*)d_in[7];
    const float* AW2 = (const float*)d_in[8];
    const float* AW23= (const float*)d_in[9];
    float* out = (float*)d_out;

    wpack_kernel<<<528, 512>>>(LW1, AW12, AW2, LW2, AW1, AW23);

    cudaFuncSetAttribute(gemm_f16_kernel,
                         cudaFuncAttributeMaxDynamicSharedMemorySize, SMEM_BYTES);
    gemm_f16_kernel<<<N_ROW_TILES * 6, NTHREADS, SMEM_BYTES>>>(xc, xp);

    epilogue_kernel<<<B_ROWS / 8, 256>>>(LB1, LB2, out);
}